// round 9
// baseline (speedup 1.0000x reference)
#include <cuda_runtime.h>

#define NT     256
#define ROWS   16
#define IT     4

__device__ double       g_sum;   // zero-init; reset by last block each run
__device__ double       g_adj;
__device__ unsigned int g_cnt;   // monotonic arrival counter (mod gridsize)

static __device__ __forceinline__ float sqa(float x) {
    float y; asm("sqrt.approx.f32 %0,%1;" : "=f"(y) : "f"(x)); return y;
}

// d2 = (||p_i-p_j|| - ||t_i-t_j||)^2 via one-sqrt identity.
// P/T hold (-2x, -2y, -2z, |.|^2) for row i.
static __device__ __forceinline__ float elem_d2(
    const float4& P, const float4& T,
    float px, float py, float pz, float pw,
    float tx, float ty, float tz, float tw)
{
    float sqp = fmaf(P.x, px, fmaf(P.y, py, fmaf(P.z, pz, P.w + pw)));
    float sqt = fmaf(T.x, tx, fmaf(T.y, ty, fmaf(T.z, tz, T.w + tw)));
    float rt  = sqa(fmaxf(sqp * sqt, 0.f));
    return fmaf(-2.f, rt, sqp + sqt);
}

extern __shared__ float s_raw[];   // 8 SoA arrays of N floats (conflict-free LDS.128)

template <int NC>   // NC>0: compile-time N (batched path); NC==0: runtime N
__global__ void __launch_bounds__(NT, 2)
loss_kernel(const float* __restrict__ preds,
            const float* __restrict__ targets,
            const float* __restrict__ adj,
            float* __restrict__ out,
            int Nrt)
{
    const int N  = (NC > 0) ? NC : Nrt;
    const int N4 = N >> 2;

    const int b    = blockIdx.y;
    const int row0 = blockIdx.x * ROWS;

    float* spx = s_raw;          float* spy = spx + N;
    float* spz = spy + N;        float* spw = spz + N;
    float* stx = spw + N;        float* sty = stx + N;
    float* stz = sty + N;        float* stw = stz + N;

    // Stage all N points + squared norms into SMEM (SoA, 64KB)
    {
        const float* pb = preds   + (size_t)b * N * 3;
        const float* tb = targets + (size_t)b * N * 3;
        for (int k = threadIdx.x; k < N; k += NT) {
            float x = pb[3*k], y = pb[3*k+1], z = pb[3*k+2];
            spx[k] = x; spy[k] = y; spz[k] = z; spw[k] = fmaf(x, x, fmaf(y, y, z*z));
            float u = tb[3*k], v = tb[3*k+1], w = tb[3*k+2];
            stx[k] = u; sty[k] = v; stz[k] = w; stw[k] = fmaf(u, u, fmaf(v, v, w*w));
        }
    }
    __syncthreads();

    float acc = 0.f, accA = 0.f;
    const float4* adjT = (const float4*)(adj + (size_t)b * N * N);

    for (int ig = 0; ig < ROWS; ig += IT) {
        const int rbase = row0 + ig;

        // Row constants from SMEM (broadcast LDS), pre-scaled by -2
        float4 P[IT], T[IT];
        #pragma unroll
        for (int r = 0; r < IT; r++) {
            int k = rbase + r;
            P[r] = make_float4(-2.f*spx[k], -2.f*spy[k], -2.f*spz[k], spw[k]);
            T[r] = make_float4(-2.f*stx[k], -2.f*sty[k], -2.f*stz[k], stw[k]);
        }

        const float4* aR = adjT + (size_t)rbase * N4 + threadIdx.x;

        if (NC > 0) {
            constexpr int JJ = (NC > 0 ? NC/4/NT : 1);   // 2 for N=2048

            // Batch ALL adj loads of this ig-block (MLP=8, issued a full
            // compute block ahead of use). Points stay transient per-jj.
            float4 a4[JJ][IT];
            #pragma unroll
            for (int jj = 0; jj < JJ; jj++)
                #pragma unroll
                for (int r = 0; r < IT; r++)
                    a4[jj][r] = aR[r * N4 + jj * NT];

            #pragma unroll
            for (int jj = 0; jj < JJ; jj++) {
                const int jv = threadIdx.x + jj * NT;
                float4 jpx = ((const float4*)spx)[jv];
                float4 jpy = ((const float4*)spy)[jv];
                float4 jpz = ((const float4*)spz)[jv];
                float4 jpw = ((const float4*)spw)[jv];
                float4 jtx = ((const float4*)stx)[jv];
                float4 jty = ((const float4*)sty)[jv];
                float4 jtz = ((const float4*)stz)[jv];
                float4 jtw = ((const float4*)stw)[jv];

                #pragma unroll
                for (int r = 0; r < IT; r++) {
                    float4 a = a4[jj][r];
                    acc = fmaf(elem_d2(P[r], T[r], jpx.x, jpy.x, jpz.x, jpw.x,
                                                    jtx.x, jty.x, jtz.x, jtw.x), a.x, acc);
                    acc = fmaf(elem_d2(P[r], T[r], jpx.y, jpy.y, jpz.y, jpw.y,
                                                    jtx.y, jty.y, jtz.y, jtw.y), a.y, acc);
                    acc = fmaf(elem_d2(P[r], T[r], jpx.z, jpy.z, jpz.z, jpw.z,
                                                    jtx.z, jty.z, jtz.z, jtw.z), a.z, acc);
                    acc = fmaf(elem_d2(P[r], T[r], jpx.w, jpy.w, jpz.w, jpw.w,
                                                    jtx.w, jty.w, jtz.w, jtw.w), a.w, acc);
                    accA += (a.x + a.y) + (a.z + a.w);
                }
            }
        } else {
            // Generic runtime-N path (R6 structure)
            for (int jv = threadIdx.x; jv < N4; jv += NT) {
                float4 a4[IT];
                #pragma unroll
                for (int r = 0; r < IT; r++) a4[r] = aR[r * N4 + (jv - threadIdx.x)];
                float4 jpx = ((const float4*)spx)[jv];
                float4 jpy = ((const float4*)spy)[jv];
                float4 jpz = ((const float4*)spz)[jv];
                float4 jpw = ((const float4*)spw)[jv];
                float4 jtx = ((const float4*)stx)[jv];
                float4 jty = ((const float4*)sty)[jv];
                float4 jtz = ((const float4*)stz)[jv];
                float4 jtw = ((const float4*)stw)[jv];
                #pragma unroll
                for (int r = 0; r < IT; r++) {
                    float4 a = a4[r];
                    acc = fmaf(elem_d2(P[r], T[r], jpx.x, jpy.x, jpz.x, jpw.x,
                                                    jtx.x, jty.x, jtz.x, jtw.x), a.x, acc);
                    acc = fmaf(elem_d2(P[r], T[r], jpx.y, jpy.y, jpz.y, jpw.y,
                                                    jtx.y, jty.y, jtz.y, jtw.y), a.y, acc);
                    acc = fmaf(elem_d2(P[r], T[r], jpx.z, jpy.z, jpz.z, jpw.z,
                                                    jtx.z, jty.z, jtz.z, jtw.z), a.z, acc);
                    acc = fmaf(elem_d2(P[r], T[r], jpx.w, jpy.w, jpz.w, jpw.w,
                                                    jtx.w, jty.w, jtz.w, jtw.w), a.w, acc);
                    accA += (a.x + a.y) + (a.z + a.w);
                }
            }
        }
    }

    // warp reduce
    #pragma unroll
    for (int off = 16; off > 0; off >>= 1) {
        acc  += __shfl_down_sync(0xffffffffu, acc,  off);
        accA += __shfl_down_sync(0xffffffffu, accA, off);
    }
    __shared__ float2 wsum[NT / 32];
    int wid = threadIdx.x >> 5, lane = threadIdx.x & 31;
    if (lane == 0) wsum[wid] = make_float2(acc, accA);
    __syncthreads();
    if (wid == 0) {
        float2 v = (lane < NT / 32) ? wsum[lane] : make_float2(0.f, 0.f);
        #pragma unroll
        for (int off = 4; off > 0; off >>= 1) {
            v.x += __shfl_down_sync(0xffffffffu, v.x, off);
            v.y += __shfl_down_sync(0xffffffffu, v.y, off);
        }
        if (lane == 0) {
            atomicAdd(&g_sum, (double)v.x);
            atomicAdd(&g_adj, (double)v.y);
            __threadfence();
            unsigned int nb  = gridDim.x * gridDim.y;
            unsigned int old = atomicAdd(&g_cnt, 1u);
            if (old % nb == nb - 1u) {            // last block of this run
                __threadfence();
                double s = atomicAdd(&g_sum, 0.0);
                double n = atomicAdd(&g_adj, 0.0);
                out[0] = (float)(s / n);
                g_sum = 0.0;                       // reset for next graph replay
                g_adj = 0.0;
            }
        }
    }
}

extern "C" void kernel_launch(void* const* d_in, const int* in_sizes, int n_in,
                              void* d_out, int out_size)
{
    const float* preds   = (const float*)d_in[0];
    const float* targets = (const float*)d_in[1];
    const float* adj     = (const float*)d_in[2];

    long long psz   = in_sizes[0];          // B*N*3
    long long adjsz = in_sizes[2];          // B*N*N
    int N = (int)(3LL * adjsz / psz);       // 2048
    int B = (int)(psz / (3LL * N));         // 8

    size_t smem = (size_t)8 * N * sizeof(float);  // 64KB
    dim3 grid(N / ROWS, B);

    if (N == 2048) {
        cudaFuncSetAttribute(loss_kernel<2048>, cudaFuncAttributeMaxDynamicSharedMemorySize, (int)smem);
        loss_kernel<2048><<<grid, NT, smem>>>(preds, targets, adj, (float*)d_out, N);
    } else {
        cudaFuncSetAttribute(loss_kernel<0>, cudaFuncAttributeMaxDynamicSharedMemorySize, (int)smem);
        loss_kernel<0><<<grid, NT, smem>>>(preds, targets, adj, (float*)d_out, N);
    }
}